// round 2
// baseline (speedup 1.0000x reference)
#include <cuda_runtime.h>
#include <cstdint>

// ---------------------------------------------------------------------------
// GroupEmbedding, fully fused: one CTA per group.
//   out[g,:] = sum_{u in grpseg(g)} ( sum_{j in behseg(u)} item[bitem[j],:]*cnt[j] )
//              ⊙ user_table[user_ids[u],:] * (user_ids[u]!=0)
// user_group_ids and behavior_user_ids are SORTED -> binary-search segments.
// Deterministic: fixed per-warp user order + fixed-order smem tree reduce.
// ---------------------------------------------------------------------------

#define EMB 128
#define WARPS 8
#define THREADS (WARPS * 32)

__device__ __forceinline__ int lower_bound_i32(const int* __restrict__ a, int n, int key) {
    int lo = 0, hi = n;
    while (lo < hi) {
        int m = (lo + hi) >> 1;
        if (__ldg(a + m) < key) lo = m + 1; else hi = m;
    }
    return lo;
}

__global__ void __launch_bounds__(THREADS) group_embedding_fused(
    const int* __restrict__ user_ids,
    const int* __restrict__ ugid,        // sorted group id per user
    const int* __restrict__ bitem,
    const float* __restrict__ bcnt,
    const int* __restrict__ buid,        // sorted user id per behavior
    const float* __restrict__ user_table,
    const float* __restrict__ item_table,
    float* __restrict__ out,
    int n_users, int n_beh)
{
    const int g    = blockIdx.x;
    const int lane = threadIdx.x & 31;
    const int w    = threadIdx.x >> 5;
    const int col  = lane * 4;

    __shared__ float s_part[WARPS * EMB];

    // --- group's user segment [us, ueend) ---
    const int us    = lower_bound_i32(ugid, n_users, g);
    const int ueend = lower_bound_i32(ugid, n_users, g + 1);
    const int nu    = ueend - us;

    // contiguous chunk of users for this warp
    const int per = (nu + WARPS - 1) / WARPS;
    const int u0  = us + w * per;
    const int u1  = min(u0 + per, ueend);

    float4 gacc = make_float4(0.f, 0.f, 0.f, 0.f);

    if (u0 < u1) {
        // behavior segment start for first user; ends chain forward
        int bs = lower_bound_i32(buid, n_beh, u0);

        for (int u = u0; u < u1; u++) {
            const int be = lower_bound_i32(buid, n_beh, u + 1);

            float4 acc = make_float4(0.f, 0.f, 0.f, 0.f);
            int j = bs;
            // unroll x4 for memory-level parallelism on the gather
            for (; j + 3 < be; j += 4) {
                int   i0 = __ldg(bitem + j + 0);
                int   i1 = __ldg(bitem + j + 1);
                int   i2 = __ldg(bitem + j + 2);
                int   i3 = __ldg(bitem + j + 3);
                float c0 = __ldg(bcnt + j + 0);
                float c1 = __ldg(bcnt + j + 1);
                float c2 = __ldg(bcnt + j + 2);
                float c3 = __ldg(bcnt + j + 3);
                float4 v0 = *reinterpret_cast<const float4*>(item_table + (size_t)i0 * EMB + col);
                float4 v1 = *reinterpret_cast<const float4*>(item_table + (size_t)i1 * EMB + col);
                float4 v2 = *reinterpret_cast<const float4*>(item_table + (size_t)i2 * EMB + col);
                float4 v3 = *reinterpret_cast<const float4*>(item_table + (size_t)i3 * EMB + col);
                acc.x += c0 * v0.x; acc.y += c0 * v0.y; acc.z += c0 * v0.z; acc.w += c0 * v0.w;
                acc.x += c1 * v1.x; acc.y += c1 * v1.y; acc.z += c1 * v1.z; acc.w += c1 * v1.w;
                acc.x += c2 * v2.x; acc.y += c2 * v2.y; acc.z += c2 * v2.z; acc.w += c2 * v2.w;
                acc.x += c3 * v3.x; acc.y += c3 * v3.y; acc.z += c3 * v3.z; acc.w += c3 * v3.w;
            }
            for (; j < be; j++) {
                int   i0 = __ldg(bitem + j);
                float c0 = __ldg(bcnt + j);
                float4 v0 = *reinterpret_cast<const float4*>(item_table + (size_t)i0 * EMB + col);
                acc.x += c0 * v0.x; acc.y += c0 * v0.y; acc.z += c0 * v0.z; acc.w += c0 * v0.w;
            }
            bs = be;

            // user embedding with padding_idx = 0, fold into group accumulator
            const int uid = __ldg(user_ids + u);
            if (uid != 0) {
                float4 uev = *reinterpret_cast<const float4*>(user_table + (size_t)uid * EMB + col);
                gacc.x += acc.x * uev.x;
                gacc.y += acc.y * uev.y;
                gacc.z += acc.z * uev.z;
                gacc.w += acc.w * uev.w;
            }
        }
    }

    // deterministic fixed-order reduction across the 8 warps
    *reinterpret_cast<float4*>(s_part + w * EMB + col) = gacc;
    __syncthreads();

    if (threadIdx.x < EMB) {
        const int t = threadIdx.x;
        float r = 0.f;
#pragma unroll
        for (int ww = 0; ww < WARPS; ww++) r += s_part[ww * EMB + t];
        out[(size_t)g * EMB + t] = r;
    }
}

extern "C" void kernel_launch(void* const* d_in, const int* in_sizes, int n_in,
                              void* d_out, int out_size)
{
    const int*   user_ids   = (const int*)  d_in[0];
    const int*   ugid       = (const int*)  d_in[1];
    const int*   bitem      = (const int*)  d_in[2];
    const float* bcnt       = (const float*)d_in[3];
    const int*   buid       = (const int*)  d_in[4];
    const float* user_table = (const float*)d_in[5];
    const float* item_table = (const float*)d_in[6];

    const int n_users    = in_sizes[0];
    const int n_beh      = in_sizes[2];
    const int num_groups = out_size / EMB;

    float* out = (float*)d_out;

    group_embedding_fused<<<num_groups, THREADS>>>(
        user_ids, ugid, bitem, bcnt, buid, user_table, item_table,
        out, n_users, n_beh);
}